// round 1
// baseline (speedup 1.0000x reference)
#include <cuda_runtime.h>
#include <math.h>

#define H_      384
#define W_      512
#define HW_     (H_ * W_)        /* 196608 */
#define B_      4
#define NPRED_  12
#define NBX     192              /* blocks per pred in kernel A */
#define NTHR    256

/* per-(pred, block) partials — device globals, no allocation */
__device__ float g_psum[NPRED_ * NBX];
__device__ float g_pcnt[NPRED_ * NBX];
__device__ float g_pmask[NBX];

__device__ __forceinline__ float lse2f(float x, float y) {
    float m = fmaxf(x, y);
    float d = fabsf(x - y);
    return m + __logf(1.0f + __expf(-d));
}

__global__ __launch_bounds__(NTHR) void loss_partial_kernel(
    const float* __restrict__ flow,   /* (12,4,2,H,W) */
    const float* __restrict__ info,   /* (12,4,4,H,W) */
    const float* __restrict__ gt,     /* (4,2,H,W) */
    const float* __restrict__ valid)  /* (4,1,H,W) */
{
    const int n = blockIdx.y;
    const float LN2   = 0.69314718055994530942f;
    const float MAXF2 = (float)(H_ * W_);   /* mag < sqrt(H*W)  <=>  mag^2 < H*W */

    float sum  = 0.0f;
    int   cnt  = 0;
    int   mcnt = 0;

    const int NG  = (B_ * HW_) / 4;  /* float4 groups over (b, hw) = 196608 */
    const int HW4 = HW_ / 4;

    for (int g = blockIdx.x * NTHR + threadIdx.x; g < NG; g += NBX * NTHR) {
        const int b  = g / HW4;
        const int hw = (g - b * HW4) * 4;

        const float4 gx4 = *(const float4*)(gt    + (size_t)(b * 2 + 0) * HW_ + hw);
        const float4 gy4 = *(const float4*)(gt    + (size_t)(b * 2 + 1) * HW_ + hw);
        const float4 vv4 = *(const float4*)(valid + (size_t)b * HW_ + hw);

        const size_t fb = (size_t)((n * B_ + b) * 2) * HW_ + hw;
        const float4 fx4 = *(const float4*)(flow + fb);
        const float4 fy4 = *(const float4*)(flow + fb + HW_);

        const size_t ib = (size_t)((n * B_ + b) * 4) * HW_ + hw;
        const float4 a04 = *(const float4*)(info + ib);
        const float4 a14 = *(const float4*)(info + ib + 1 * (size_t)HW_);
        const float4 b24 = *(const float4*)(info + ib + 2 * (size_t)HW_);
        const float4 b34 = *(const float4*)(info + ib + 3 * (size_t)HW_);

        float gxv[4], gyv[4], vvv[4], fxv[4], fyv[4], a0v[4], a1v[4], b2v[4], b3v[4];
        *(float4*)gxv = gx4;  *(float4*)gyv = gy4;  *(float4*)vvv = vv4;
        *(float4*)fxv = fx4;  *(float4*)fyv = fy4;
        *(float4*)a0v = a04;  *(float4*)a1v = a14;
        *(float4*)b2v = b24;  *(float4*)b3v = b34;

        #pragma unroll
        for (int j = 0; j < 4; j++) {
            const float gx = gxv[j], gy = gyv[j];
            const bool m1 = (gx * gx + gy * gy < MAXF2) && (vvv[j] != 0.0f);
            mcnt += m1 ? 1 : 0;

            const float a0  = a0v[j];
            const float a1  = a1v[j];
            const float lb0 = fminf(fmaxf(b2v[j], 0.0f), 10.0f);
            const float lb1 = fminf(fmaxf(b3v[j], 0.0f), 0.0f);
            const float eb0 = __expf(-lb0);
            const float eb1 = __expf(-lb1);

            const float lse_a = lse2f(a0, a1);
            const float t0 = a0 - LN2 - lb0;
            const float t1 = a1 - LN2 - lb1;

            const float dx  = fabsf(gx - fxv[j]);
            const float nfx = lse_a - lse2f(t0 - dx * eb0, t1 - dx * eb1);
            const float dy  = fabsf(gy - fyv[j]);
            const float nfy = lse_a - lse2f(t0 - dy * eb0, t1 - dy * eb1);

            if (isfinite(nfx) && m1) { sum += nfx; cnt++; }
            if (isfinite(nfy) && m1) { sum += nfy; cnt++; }
        }
    }

    /* ---- block reduction ---- */
    float fcnt  = (float)cnt;
    float fmcnt = (float)mcnt;
    #pragma unroll
    for (int o = 16; o > 0; o >>= 1) {
        sum   += __shfl_down_sync(0xFFFFFFFFu, sum,   o);
        fcnt  += __shfl_down_sync(0xFFFFFFFFu, fcnt,  o);
        fmcnt += __shfl_down_sync(0xFFFFFFFFu, fmcnt, o);
    }
    __shared__ float ssum[NTHR / 32], scnt[NTHR / 32], smc[NTHR / 32];
    const int wid  = threadIdx.x >> 5;
    const int lane = threadIdx.x & 31;
    if (lane == 0) { ssum[wid] = sum; scnt[wid] = fcnt; smc[wid] = fmcnt; }
    __syncthreads();
    if (threadIdx.x == 0) {
        float bs = 0.0f, bc = 0.0f, bm = 0.0f;
        #pragma unroll
        for (int w = 0; w < NTHR / 32; w++) { bs += ssum[w]; bc += scnt[w]; bm += smc[w]; }
        g_psum[n * NBX + blockIdx.x] = bs;
        g_pcnt[n * NBX + blockIdx.x] = bc;
        if (n == 0) g_pmask[blockIdx.x] = bm;
    }
}

__global__ void loss_final_kernel(float* __restrict__ out) {
    const int t = threadIdx.x;   /* 32 threads */
    __shared__ float sres[NPRED_];
    __shared__ float smask;
    if (t < NPRED_) {
        float s = 0.0f, c = 0.0f;
        for (int i = 0; i < NBX; i++) {
            s += g_psum[t * NBX + i];
            c += g_pcnt[t * NBX + i];
        }
        sres[t] = s / fmaxf(c, 1.0f);
    }
    if (t == 31) {
        float mc = 0.0f;
        for (int i = 0; i < NBX; i++) mc += g_pmask[i];
        smask = mc;
    }
    __syncthreads();
    if (t == 0) {
        float loss = 0.0f;
        #pragma unroll
        for (int i = 0; i < NPRED_; i++) loss += sres[i];
        const float mean_mask = smask * (1.0f / (float)(B_ * HW_));
        out[0] = (mean_mask < 0.25f) ? 0.0f : loss;
    }
}

extern "C" void kernel_launch(void* const* d_in, const int* in_sizes, int n_in,
                              void* d_out, int out_size) {
    const float* flow  = (const float*)d_in[0];  /* flow_preds (12,4,2,384,512) */
    const float* info  = (const float*)d_in[1];  /* info_preds (12,4,4,384,512) */
    const float* gt    = (const float*)d_in[2];  /* flow_gt    (4,2,384,512)    */
    const float* valid = (const float*)d_in[3];  /* valid      (4,1,384,512)    */
    (void)in_sizes; (void)n_in; (void)out_size;

    dim3 grid(NBX, NPRED_);
    loss_partial_kernel<<<grid, NTHR>>>(flow, info, gt, valid);
    loss_final_kernel<<<1, 32>>>((float*)d_out);
}

// round 2
// speedup vs baseline: 1.2353x; 1.2353x over previous
#include <cuda_runtime.h>
#include <math.h>

#define H_      384
#define W_      512
#define HW_     (H_ * W_)        /* 196608 */
#define B_      4
#define NPRED_  12
#define NBX     192              /* blocks per pred */
#define NTHR    256

/* per-(pred, block) partials — device globals, no allocation */
__device__ float    g_psum[NPRED_ * NBX];
__device__ float    g_pcnt[NPRED_ * NBX];
__device__ float    g_pmask[NBX];
__device__ unsigned g_ticket;    /* zero-initialized; reset by last block */

__device__ __forceinline__ float lse2f(float x, float y) {
    float m = fmaxf(x, y);
    float d = fabsf(x - y);
    return m + __logf(1.0f + __expf(-d));
}

__global__ __launch_bounds__(NTHR) void loss_fused_kernel(
    const float* __restrict__ flow,   /* (12,4,2,H,W) */
    const float* __restrict__ info,   /* (12,4,4,H,W) */
    const float* __restrict__ gt,     /* (4,2,H,W) */
    const float* __restrict__ valid,  /* (4,1,H,W) */
    float* __restrict__ out)
{
    const int n = blockIdx.y;
    const float LN2   = 0.69314718055994530942f;
    const float MAXF2 = (float)(H_ * W_);   /* mag < sqrt(H*W)  <=>  mag^2 < H*W */

    float sum  = 0.0f;
    int   cnt  = 0;
    int   mcnt = 0;

    const int NG  = (B_ * HW_) / 4;  /* float4 groups over (b, hw) = 196608 */
    const int HW4 = HW_ / 4;

    for (int g = blockIdx.x * NTHR + threadIdx.x; g < NG; g += NBX * NTHR) {
        const int b  = g / HW4;
        const int hw = (g - b * HW4) * 4;

        /* gt/valid: reused by all 12 preds — keep cached */
        const float4 gx4 = __ldg((const float4*)(gt    + (size_t)(b * 2 + 0) * HW_ + hw));
        const float4 gy4 = __ldg((const float4*)(gt    + (size_t)(b * 2 + 1) * HW_ + hw));
        const float4 vv4 = __ldg((const float4*)(valid + (size_t)b * HW_ + hw));

        /* flow/info: streamed once — evict-first */
        const size_t fb = (size_t)((n * B_ + b) * 2) * HW_ + hw;
        const float4 fx4 = __ldcs((const float4*)(flow + fb));
        const float4 fy4 = __ldcs((const float4*)(flow + fb + HW_));

        const size_t ib = (size_t)((n * B_ + b) * 4) * HW_ + hw;
        const float4 a04 = __ldcs((const float4*)(info + ib));
        const float4 a14 = __ldcs((const float4*)(info + ib + 1 * (size_t)HW_));
        const float4 b24 = __ldcs((const float4*)(info + ib + 2 * (size_t)HW_));
        const float4 b34 = __ldcs((const float4*)(info + ib + 3 * (size_t)HW_));

        float gxv[4], gyv[4], vvv[4], fxv[4], fyv[4], a0v[4], a1v[4], b2v[4], b3v[4];
        *(float4*)gxv = gx4;  *(float4*)gyv = gy4;  *(float4*)vvv = vv4;
        *(float4*)fxv = fx4;  *(float4*)fyv = fy4;
        *(float4*)a0v = a04;  *(float4*)a1v = a14;
        *(float4*)b2v = b24;  *(float4*)b3v = b34;

        #pragma unroll
        for (int j = 0; j < 4; j++) {
            const float gx = gxv[j], gy = gyv[j];
            const bool m1 = (gx * gx + gy * gy < MAXF2) && (vvv[j] != 0.0f);
            mcnt += m1 ? 1 : 0;

            const float a0  = a0v[j];
            const float a1  = a1v[j];
            const float lb0 = fminf(fmaxf(b2v[j], 0.0f), 10.0f);
            const float lb1 = fminf(fmaxf(b3v[j], 0.0f), 0.0f);
            const float eb0 = __expf(-lb0);
            const float eb1 = __expf(-lb1);

            const float lse_a = lse2f(a0, a1);
            const float t0 = a0 - LN2 - lb0;
            const float t1 = a1 - LN2 - lb1;

            const float dx  = fabsf(gx - fxv[j]);
            const float nfx = lse_a - lse2f(t0 - dx * eb0, t1 - dx * eb1);
            const float dy  = fabsf(gy - fyv[j]);
            const float nfy = lse_a - lse2f(t0 - dy * eb0, t1 - dy * eb1);

            if (isfinite(nfx) && m1) { sum += nfx; cnt++; }
            if (isfinite(nfy) && m1) { sum += nfy; cnt++; }
        }
    }

    /* ---- block reduction ---- */
    float fcnt  = (float)cnt;
    float fmcnt = (float)mcnt;
    #pragma unroll
    for (int o = 16; o > 0; o >>= 1) {
        sum   += __shfl_down_sync(0xFFFFFFFFu, sum,   o);
        fcnt  += __shfl_down_sync(0xFFFFFFFFu, fcnt,  o);
        fmcnt += __shfl_down_sync(0xFFFFFFFFu, fmcnt, o);
    }
    __shared__ float ssum[NTHR / 32], scnt[NTHR / 32], smc[NTHR / 32];
    const int wid  = threadIdx.x >> 5;
    const int lane = threadIdx.x & 31;
    if (lane == 0) { ssum[wid] = sum; scnt[wid] = fcnt; smc[wid] = fmcnt; }
    __syncthreads();
    if (threadIdx.x == 0) {
        float bs = 0.0f, bc = 0.0f, bm = 0.0f;
        #pragma unroll
        for (int w = 0; w < NTHR / 32; w++) { bs += ssum[w]; bc += scnt[w]; bm += smc[w]; }
        g_psum[n * NBX + blockIdx.x] = bs;
        g_pcnt[n * NBX + blockIdx.x] = bc;
        if (n == 0) g_pmask[blockIdx.x] = bm;
    }

    /* ---- last-block-done final reduction (deterministic: fixed partials,
            fixed reduction order; only the reducing block's identity varies) ---- */
    __shared__ unsigned s_islast;
    __threadfence();
    if (threadIdx.x == 0) {
        unsigned tkt = atomicAdd(&g_ticket, 1u);
        s_islast = (tkt == (unsigned)(NPRED_ * NBX - 1)) ? 1u : 0u;
    }
    __syncthreads();
    if (!s_islast) return;

    const int t = threadIdx.x;
    __shared__ float s_res[NPRED_];
    __shared__ float s_m[2];

    if (t < 192) {
        /* 16 threads per pred, each sums 12 partials */
        const int pred = t >> 4;
        const int sub  = t & 15;
        float s = 0.0f, c = 0.0f;
        #pragma unroll
        for (int i = sub; i < NBX; i += 16) {
            s += g_psum[pred * NBX + i];
            c += g_pcnt[pred * NBX + i];
        }
        #pragma unroll
        for (int o = 8; o > 0; o >>= 1) {
            s += __shfl_down_sync(0xFFFFFFFFu, s, o, 16);
            c += __shfl_down_sync(0xFFFFFFFFu, c, o, 16);
        }
        if (sub == 0) s_res[pred] = s / fmaxf(c, 1.0f);
    } else {
        /* threads 192..255 reduce the 192 mask partials */
        const int i0 = t - 192;
        float m = 0.0f;
        #pragma unroll
        for (int i = i0; i < NBX; i += 64) m += g_pmask[i];
        #pragma unroll
        for (int o = 16; o > 0; o >>= 1) m += __shfl_down_sync(0xFFFFFFFFu, m, o);
        if (((t - 192) & 31) == 0) s_m[(t - 192) >> 5] = m;
    }
    __syncthreads();
    if (t == 0) {
        float loss = 0.0f;
        #pragma unroll
        for (int i = 0; i < NPRED_; i++) loss += s_res[i];
        const float mean_mask = (s_m[0] + s_m[1]) * (1.0f / (float)(B_ * HW_));
        out[0] = (mean_mask < 0.25f) ? 0.0f : loss;
        g_ticket = 0;   /* reset for the next graph replay */
    }
}

extern "C" void kernel_launch(void* const* d_in, const int* in_sizes, int n_in,
                              void* d_out, int out_size) {
    const float* flow  = (const float*)d_in[0];  /* flow_preds (12,4,2,384,512) */
    const float* info  = (const float*)d_in[1];  /* info_preds (12,4,4,384,512) */
    const float* gt    = (const float*)d_in[2];  /* flow_gt    (4,2,384,512)    */
    const float* valid = (const float*)d_in[3];  /* valid      (4,1,384,512)    */
    (void)in_sizes; (void)n_in; (void)out_size;

    dim3 grid(NBX, NPRED_);
    loss_fused_kernel<<<grid, NTHR>>>(flow, info, gt, valid, (float*)d_out);
}

// round 3
// speedup vs baseline: 1.3816x; 1.1184x over previous
#include <cuda_runtime.h>
#include <math.h>

#define H_      384
#define W_      512
#define HW_     (H_ * W_)        /* 196608 */
#define B_      4
#define NPRED_  12
#define NBX     192              /* blocks per pred */
#define NTHR    256

/* per-(pred, block) partials — device globals, no allocation */
__device__ float    g_psum[NPRED_ * NBX];
__device__ float    g_pcnt[NPRED_ * NBX];
__device__ float    g_pmask[NBX];
__device__ unsigned g_ticket;    /* zero-initialized; reset by last block */

__device__ __forceinline__ float lse2f(float x, float y) {
    float m = fmaxf(x, y);
    float d = fabsf(x - y);
    return m + __logf(1.0f + __expf(-d));
}

/* NOTE: log_b[:,1] = clip(info[:,3], 0.0, 0.0) == 0 for all finite inputs,
   so info channel 3 is never read: lb1 = 0, exp(-lb1) = 1, t1 = a1 - ln2. */

__global__ __launch_bounds__(NTHR) void loss_fused_kernel(
    const float* __restrict__ flow,   /* (12,4,2,H,W) */
    const float* __restrict__ info,   /* (12,4,4,H,W) */
    const float* __restrict__ gt,     /* (4,2,H,W) */
    const float* __restrict__ valid,  /* (4,1,H,W) */
    float* __restrict__ out)
{
    const int n = blockIdx.y;
    const float LN2   = 0.69314718055994530942f;
    const float MAXF2 = (float)(H_ * W_);   /* mag < sqrt(H*W)  <=>  mag^2 < H*W */

    float sum  = 0.0f;
    int   cnt  = 0;
    int   mcnt = 0;

    const int NG  = (B_ * HW_) / 4;  /* float4 groups over (b, hw) = 196608 */
    const int HW4 = HW_ / 4;

    #pragma unroll 2
    for (int g = blockIdx.x * NTHR + threadIdx.x; g < NG; g += NBX * NTHR) {
        const int b  = g / HW4;
        const int hw = (g - b * HW4) * 4;

        /* gt/valid: reused by all 12 preds — keep L2-cached */
        const float4 gx4 = __ldg((const float4*)(gt    + (size_t)(b * 2 + 0) * HW_ + hw));
        const float4 gy4 = __ldg((const float4*)(gt    + (size_t)(b * 2 + 1) * HW_ + hw));
        const float4 vv4 = __ldg((const float4*)(valid + (size_t)b * HW_ + hw));

        /* flow/info: streamed once — evict-first */
        const size_t fb = (size_t)((n * B_ + b) * 2) * HW_ + hw;
        const float4 fx4 = __ldcs((const float4*)(flow + fb));
        const float4 fy4 = __ldcs((const float4*)(flow + fb + HW_));

        const size_t ib = (size_t)((n * B_ + b) * 4) * HW_ + hw;
        const float4 a04 = __ldcs((const float4*)(info + ib));
        const float4 a14 = __ldcs((const float4*)(info + ib + 1 * (size_t)HW_));
        const float4 b24 = __ldcs((const float4*)(info + ib + 2 * (size_t)HW_));
        /* info channel 3 (b34) intentionally NOT loaded: clip(.,0,0) == 0 */

        float gxv[4], gyv[4], vvv[4], fxv[4], fyv[4], a0v[4], a1v[4], b2v[4];
        *(float4*)gxv = gx4;  *(float4*)gyv = gy4;  *(float4*)vvv = vv4;
        *(float4*)fxv = fx4;  *(float4*)fyv = fy4;
        *(float4*)a0v = a04;  *(float4*)a1v = a14;
        *(float4*)b2v = b24;

        #pragma unroll
        for (int j = 0; j < 4; j++) {
            const float gx = gxv[j], gy = gyv[j];
            const bool m1 = (gx * gx + gy * gy < MAXF2) && (vvv[j] != 0.0f);
            mcnt += m1 ? 1 : 0;

            const float a0  = a0v[j];
            const float a1  = a1v[j];
            const float lb0 = fminf(fmaxf(b2v[j], 0.0f), 10.0f);
            const float eb0 = __expf(-lb0);

            const float lse_a = lse2f(a0, a1);
            const float t0 = a0 - LN2 - lb0;
            const float t1 = a1 - LN2;          /* lb1 == 0 */

            const float dx  = fabsf(gx - fxv[j]);
            const float nfx = lse_a - lse2f(t0 - dx * eb0, t1 - dx);
            const float dy  = fabsf(gy - fyv[j]);
            const float nfy = lse_a - lse2f(t0 - dy * eb0, t1 - dy);

            if (isfinite(nfx) && m1) { sum += nfx; cnt++; }
            if (isfinite(nfy) && m1) { sum += nfy; cnt++; }
        }
    }

    /* ---- block reduction ---- */
    float fcnt  = (float)cnt;
    float fmcnt = (float)mcnt;
    #pragma unroll
    for (int o = 16; o > 0; o >>= 1) {
        sum   += __shfl_down_sync(0xFFFFFFFFu, sum,   o);
        fcnt  += __shfl_down_sync(0xFFFFFFFFu, fcnt,  o);
        fmcnt += __shfl_down_sync(0xFFFFFFFFu, fmcnt, o);
    }
    __shared__ float ssum[NTHR / 32], scnt[NTHR / 32], smc[NTHR / 32];
    const int wid  = threadIdx.x >> 5;
    const int lane = threadIdx.x & 31;
    if (lane == 0) { ssum[wid] = sum; scnt[wid] = fcnt; smc[wid] = fmcnt; }
    __syncthreads();
    if (threadIdx.x == 0) {
        float bs = 0.0f, bc = 0.0f, bm = 0.0f;
        #pragma unroll
        for (int w = 0; w < NTHR / 32; w++) { bs += ssum[w]; bc += scnt[w]; bm += smc[w]; }
        g_psum[n * NBX + blockIdx.x] = bs;
        g_pcnt[n * NBX + blockIdx.x] = bc;
        if (n == 0) g_pmask[blockIdx.x] = bm;
    }

    /* ---- last-block-done final reduction (deterministic: fixed partials,
            fixed reduction order; only the reducing block's identity varies) ---- */
    __shared__ unsigned s_islast;
    __threadfence();
    if (threadIdx.x == 0) {
        unsigned tkt = atomicAdd(&g_ticket, 1u);
        s_islast = (tkt == (unsigned)(NPRED_ * NBX - 1)) ? 1u : 0u;
    }
    __syncthreads();
    if (!s_islast) return;

    const int t = threadIdx.x;
    __shared__ float s_res[NPRED_];
    __shared__ float s_m[2];

    if (t < 192) {
        /* 16 threads per pred, each sums 12 partials */
        const int pred = t >> 4;
        const int sub  = t & 15;
        float s = 0.0f, c = 0.0f;
        #pragma unroll
        for (int i = sub; i < NBX; i += 16) {
            s += g_psum[pred * NBX + i];
            c += g_pcnt[pred * NBX + i];
        }
        #pragma unroll
        for (int o = 8; o > 0; o >>= 1) {
            s += __shfl_down_sync(0xFFFFFFFFu, s, o, 16);
            c += __shfl_down_sync(0xFFFFFFFFu, c, o, 16);
        }
        if (sub == 0) s_res[pred] = s / fmaxf(c, 1.0f);
    } else {
        /* threads 192..255 reduce the 192 mask partials */
        const int i0 = t - 192;
        float m = 0.0f;
        #pragma unroll
        for (int i = i0; i < NBX; i += 64) m += g_pmask[i];
        #pragma unroll
        for (int o = 16; o > 0; o >>= 1) m += __shfl_down_sync(0xFFFFFFFFu, m, o);
        if (((t - 192) & 31) == 0) s_m[(t - 192) >> 5] = m;
    }
    __syncthreads();
    if (t == 0) {
        float loss = 0.0f;
        #pragma unroll
        for (int i = 0; i < NPRED_; i++) loss += s_res[i];
        const float mean_mask = (s_m[0] + s_m[1]) * (1.0f / (float)(B_ * HW_));
        out[0] = (mean_mask < 0.25f) ? 0.0f : loss;
        g_ticket = 0;   /* reset for the next graph replay */
    }
}

extern "C" void kernel_launch(void* const* d_in, const int* in_sizes, int n_in,
                              void* d_out, int out_size) {
    const float* flow  = (const float*)d_in[0];  /* flow_preds (12,4,2,384,512) */
    const float* info  = (const float*)d_in[1];  /* info_preds (12,4,4,384,512) */
    const float* gt    = (const float*)d_in[2];  /* flow_gt    (4,2,384,512)    */
    const float* valid = (const float*)d_in[3];  /* valid      (4,1,384,512)    */
    (void)in_sizes; (void)n_in; (void)out_size;

    dim3 grid(NBX, NPRED_);
    loss_fused_kernel<<<grid, NTHR>>>(flow, info, gt, valid, (float*)d_out);
}